// round 15
// baseline (speedup 1.0000x reference)
#include <cuda_runtime.h>
#include <cuda_fp16.h>
#include <math_constants.h>

// Problem constants (fixed by the dataset)
constexpr int NN = 100000;   // nodes
constexpr int EE = 1600000;  // edges
constexpr int DD = 128;      // model dim
constexpr int HH = 8;        // heads
// DH = 16, M = 3

// ---------------- scratch (static device globals; no allocation) -------------
__device__ float  g_Q[NN * DD];
__device__ __half g_KVh[NN * 256];    // per node: K[128 halfs] then V[128 halfs]
__device__ int    g_deg[NN];
__device__ int    g_rowptr[NN + 1];
__device__ int    g_cursor[NN];
__device__ int2   g_edge[EE];         // (eid, src) packed
__device__ float  g_scores[(size_t)EE * HH];  // raw scores in CSR order
__device__ int    g_bsum[128];

// ---------------- TF32 helpers ------------------------------------------------
__device__ __forceinline__ float to_tf32(float a) {
    float r; asm("cvt.rna.tf32.f32 %0, %1;" : "=f"(r) : "f"(a)); return r;
}

__device__ __forceinline__ void mma_tf32(float c[4], const unsigned a[4],
                                         const unsigned b[2]) {
    asm volatile(
        "mma.sync.aligned.m16n8k8.row.col.f32.tf32.tf32.f32 "
        "{%0,%1,%2,%3}, {%4,%5,%6,%7}, {%8,%9}, {%0,%1,%2,%3};"
        : "+f"(c[0]), "+f"(c[1]), "+f"(c[2]), "+f"(c[3])
        : "r"(a[0]), "r"(a[1]), "r"(a[2]), "r"(a[3]), "r"(b[0]), "r"(b[1]));
}

// ---------------- QKV GEMM (TF32 tensor core, cp.async W pipeline) ------------
// Block tile 64(M) x 128(N), A resident, W streamed (12 slabs of 32k, double
// buffered). 8 warps: 2(M) x 4(N); warp tile 32x32 = 2 m-tiles x 4 n-tiles.
// 68.6 KB smem + <=80 regs -> 3 CTAs/SM (24 warps) for latency hiding.
constexpr int XS = 132;            // xs row stride
constexpr int WSS = 136;           // W slab row stride
constexpr int SLABF = 32 * WSS;    // floats per slab buffer
constexpr int GEMM_SMEM = (64 * XS + 2 * SLABF) * 4;   // 68608 B

__device__ __forceinline__ void cpasync_w_slab(const float* Wsrc, float* buf,
                                               int tid) {
    unsigned sb = (unsigned)__cvta_generic_to_shared(buf);
#pragma unroll
    for (int i = 0; i < 4; ++i) {
        int idx = tid + i * 256;
        int kr = idx >> 5, c = (idx & 31) << 2;
        unsigned sa = sb + (unsigned)((kr * WSS + c) * 4);
        asm volatile("cp.async.cg.shared.global [%0], [%1], 16;\n"
                     :: "r"(sa), "l"(Wsrc + (size_t)kr * DD + c));
    }
}

__global__ __launch_bounds__(256, 3) void qkv_gemm_tc(
    const float* __restrict__ x,
    const float* __restrict__ Wq, const float* __restrict__ bq,
    const float* __restrict__ Wk, const float* __restrict__ bk,
    const float* __restrict__ Wv, const float* __restrict__ bv,
    int n)
{
    extern __shared__ float smem[];
    float* xs  = smem;               // [64 rows][XS]   tf32 values
    float* wsb = smem + 64 * XS;     // [2][32 k][WSS]  W slab double buffer

    const int tid  = threadIdx.x;
    const int lane = tid & 31;
    const int wid  = tid >> 5;
    const int warpM = wid & 1;       // 2 warps x 32 rows
    const int warpN = wid >> 1;      // 4 warps x 32 cols
    const int row0 = blockIdx.x * 64;

    // load + convert x tile [64][128]; OOB rows -> 0  (8 iters)
    for (int i = tid; i < 64 * 32; i += 256) {
        int r = i >> 5, c = (i & 31) << 2;
        float4 v = make_float4(0.f, 0.f, 0.f, 0.f);
        if (row0 + r < n) v = *(const float4*)(x + (size_t)(row0 + r) * DD + c);
        xs[r * XS + c]     = to_tf32(v.x);
        xs[r * XS + c + 1] = to_tf32(v.y);
        xs[r * XS + c + 2] = to_tf32(v.z);
        xs[r * XS + c + 3] = to_tf32(v.w);
    }

    const float* Ws[3] = {Wq, Wk, Wv};
    const float* Bs[3] = {bq, bk, bv};

    const int gidx = lane >> 2;
    const int tidx = lane & 3;

    cpasync_w_slab(Ws[0], wsb, tid);
    asm volatile("cp.async.commit_group;\n");

    float C[2][4][4];

#pragma unroll 1
    for (int ls = 0; ls < 12; ++ls) {
        const int w = ls >> 2;
        const int s = ls & 3;

        if (s == 0) {
#pragma unroll
            for (int mt = 0; mt < 2; ++mt)
#pragma unroll
                for (int nt = 0; nt < 4; ++nt)
#pragma unroll
                    for (int q = 0; q < 4; ++q) C[mt][nt][q] = 0.f;
        }

        asm volatile("cp.async.wait_group 0;\n");
        __syncthreads();

        if (ls < 11) {
            const int nls = ls + 1;
            cpasync_w_slab(Ws[nls >> 2] + (size_t)((nls & 3) * 32) * DD,
                           wsb + (nls & 1) * SLABF, tid);
            asm volatile("cp.async.commit_group;\n");
        }

        float* wb = wsb + (ls & 1) * SLABF;
        // convert slab to tf32 in place
#pragma unroll
        for (int i = 0; i < 4; ++i) {
            int idx = tid + i * 256;
            int kr = idx >> 5, c = (idx & 31) << 2;
            float4* p = (float4*)(wb + kr * WSS + c);
            float4 v = *p;
            v.x = to_tf32(v.x); v.y = to_tf32(v.y);
            v.z = to_tf32(v.z); v.w = to_tf32(v.w);
            *p = v;
        }
        __syncthreads();

#pragma unroll
        for (int k8 = 0; k8 < 4; ++k8) {
            unsigned a[2][4];
#pragma unroll
            for (int mt = 0; mt < 2; ++mt) {
                int row = warpM * 32 + mt * 16 + gidx;
                int col = s * 32 + k8 * 8 + tidx;
                a[mt][0] = __float_as_uint(xs[row * XS + col]);
                a[mt][1] = __float_as_uint(xs[(row + 8) * XS + col]);
                a[mt][2] = __float_as_uint(xs[row * XS + col + 4]);
                a[mt][3] = __float_as_uint(xs[(row + 8) * XS + col + 4]);
            }
#pragma unroll
            for (int nt = 0; nt < 4; ++nt) {
                int colb = warpN * 32 + nt * 8 + gidx;
                int krow = k8 * 8 + tidx;
                unsigned b[2];
                b[0] = __float_as_uint(wb[krow * WSS + colb]);
                b[1] = __float_as_uint(wb[(krow + 4) * WSS + colb]);
                mma_tf32(C[0][nt], a[0], b);
                mma_tf32(C[1][nt], a[1], b);
            }
        }

        if (s == 3) {
            // epilogue: bias add + store. Q fp32; K/V fp16 into g_KVh.
            const float* B = Bs[w];
#pragma unroll
            for (int nt = 0; nt < 4; ++nt) {
                int col = warpN * 32 + nt * 8 + 2 * tidx;
                float b0 = __ldg(B + col);
                float b1 = __ldg(B + col + 1);
#pragma unroll
                for (int mt = 0; mt < 2; ++mt) {
                    int r0 = row0 + warpM * 32 + mt * 16 + gidx;
                    int r1 = r0 + 8;
                    float o00 = C[mt][nt][0] + b0, o01 = C[mt][nt][1] + b1;
                    float o10 = C[mt][nt][2] + b0, o11 = C[mt][nt][3] + b1;
                    if (w == 0) {
                        if (r0 < n) *(float2*)(g_Q + (size_t)r0 * DD + col) =
                            make_float2(o00, o01);
                        if (r1 < n) *(float2*)(g_Q + (size_t)r1 * DD + col) =
                            make_float2(o10, o11);
                    } else {
                        int off = (w == 1) ? 0 : 128;
                        if (r0 < n)
                            *(__half2*)(g_KVh + (size_t)r0 * 256 + off + col) =
                                __floats2half2_rn(o00, o01);
                        if (r1 < n)
                            *(__half2*)(g_KVh + (size_t)r1 * 256 + off + col) =
                                __floats2half2_rn(o10, o11);
                    }
                }
            }
        }
        __syncthreads();
    }
}

// ---------------- CSR construction -------------------------------------------
__global__ void hist_kernel(const int* __restrict__ dst, int E) {
    int i = blockIdx.x * blockDim.x + threadIdx.x;
    if (i < E) atomicAdd(&g_deg[dst[i]], 1);
}

__global__ __launch_bounds__(1024) void scan1(int n) {
    __shared__ int sm[1024];
    const int t = threadIdx.x;
    const int i = blockIdx.x * 1024 + t;
    int v = (i < n) ? g_deg[i] : 0;
    if (i < n) g_deg[i] = 0;
    sm[t] = v;
    __syncthreads();
    for (int off = 1; off < 1024; off <<= 1) {
        int u = (t >= off) ? sm[t - off] : 0;
        __syncthreads();
        sm[t] += u;
        __syncthreads();
    }
    if (i < n) g_rowptr[i] = sm[t] - v;
    if (t == 1023) g_bsum[blockIdx.x] = sm[t];
}

__global__ __launch_bounds__(1024) void scan3(int n, int E) {
    __shared__ int soff;
    const int t = threadIdx.x;
    if (t == 0) soff = 0;
    __syncthreads();
    int acc = 0;
    for (int j = t; j < blockIdx.x; j += 1024) acc += g_bsum[j];
    if (acc) atomicAdd(&soff, acc);
    __syncthreads();
    const int i = blockIdx.x * 1024 + t;
    if (i < n) {
        int r = g_rowptr[i] + soff;
        g_rowptr[i] = r;
        g_cursor[i] = r;
    }
    if (i == 0) g_rowptr[n] = E;
}

__global__ void scatter_kernel(const int* __restrict__ src,
                               const int* __restrict__ dst, int E) {
    int i = blockIdx.x * blockDim.x + threadIdx.x;
    if (i < E) {
        int p = atomicAdd(&g_cursor[dst[i]], 1);
        g_edge[p] = make_int2(i, src[i]);
    }
}

// ---------------- per-node attention (max-free softmax) -----------------------
// One warp per node, 64-thread blocks (R14). Scores are bounded (|q.k|/4 +
// log(mix) <= ~8), so exp() cannot overflow fp32: plain sum-of-exp replaces the
// online max-rescale, removing the serial per-edge rescale chain entirely.
// Masked edges: __expf(-1e9) underflows to exactly 0.
__global__ __launch_bounds__(64) void node_attn(
    const float* __restrict__ pi, const float* __restrict__ view_w,
    float* __restrict__ ns_out, float* __restrict__ attn_out, int n)
{
    int warp = (blockIdx.x * blockDim.x + threadIdx.x) >> 5;
    if (warp >= n) return;
    const int lane = threadIdx.x & 31;
    const int h = lane >> 2;
    const int nd = warp;
    const int dsub = lane & 3;

    const float4* Q4 = (const float4*)g_Q;
    const uint2* KVu = (const uint2*)g_KVh;   // 64 uint2 per node (512B)

    const float4 qv = Q4[nd * 32 + lane];
    const float p0 = pi[nd * 24 + h * 3 + 0];
    const float p1 = pi[nd * 24 + h * 3 + 1];
    const float p2 = pi[nd * 24 + h * 3 + 2];

    const int beg = g_rowptr[nd];
    const int end = g_rowptr[nd + 1];

    float s_run = 0.f;
    float ax = 0.f, ay = 0.f, az = 0.f, aw = 0.f;

    for (int j = beg; j < end; ++j) {
        const int2 e = g_edge[j];
        const int eid = e.x;
        const int sN = e.y;

        uint2 ku = KVu[(size_t)sN * 64 + lane];
        uint2 vu = KVu[(size_t)sN * 64 + 32 + lane];
        float2 k01 = __half22float2(*(__half2*)&ku.x);
        float2 k23 = __half22float2(*(__half2*)&ku.y);

        float d = qv.x * k01.x + qv.y * k01.y + qv.z * k23.x + qv.w * k23.y;
        d += __shfl_xor_sync(0xffffffff, d, 1);
        d += __shfl_xor_sync(0xffffffff, d, 2);

        float vw0 = view_w[eid * 3 + 0];
        float vw1 = view_w[eid * 3 + 1];
        float vw2 = view_w[eid * 3 + 2];
        float mix = p0 * vw0 + p1 * vw1 + p2 * vw2;

        float sc = d * 0.25f + __logf(fmaxf(mix, 1e-8f));
        if (!(mix > 0.f)) sc = -1e9f;
        if (dsub == 0) g_scores[(size_t)j * HH + h] = sc;   // sequential write

        float p = __expf(sc);        // masked -> underflow to 0
        float2 v01 = __half22float2(*(__half2*)&vu.x);
        float2 v23 = __half22float2(*(__half2*)&vu.y);
        s_run += p;
        ax += p * v01.x;
        ay += p * v01.y;
        az += p * v23.x;
        aw += p * v23.y;
    }

    float inv = 1.f / fmaxf(s_run, 1e-8f);
    ((float4*)ns_out)[nd * 32 + lane] = make_float4(ax * inv, ay * inv,
                                                    az * inv, aw * inv);

    // sweep 2: normalize scores -> attn_out. 4 edges per iteration.
    const int h2 = lane & 7;
    const float i_h = __shfl_sync(0xffffffff, inv, h2 << 2);
    for (int j0 = beg; j0 < end; j0 += 4) {
        int j = j0 + (lane >> 3);
        if (j < end) {
            int eid = g_edge[j].x;
            float sc = g_scores[(size_t)j * HH + h2];
            float a = (sc > -1e8f) ? __expf(sc) * i_h : 0.f;
            attn_out[(size_t)eid * HH + h2] = a;
        }
    }
}

// ---------------- launch ------------------------------------------------------
extern "C" void kernel_launch(void* const* d_in, const int* in_sizes, int n_in,
                              void* d_out, int out_size) {
    const float* x   = (const float*)d_in[0];
    const float* pi  = (const float*)d_in[1];
    const float* vw  = (const float*)d_in[2];
    const float* Wq  = (const float*)d_in[3];
    const float* bq  = (const float*)d_in[4];
    const float* Wk  = (const float*)d_in[5];
    const float* bk  = (const float*)d_in[6];
    const float* Wv  = (const float*)d_in[7];
    const float* bv  = (const float*)d_in[8];
    const int*   src = (const int*)d_in[9];
    const int*   dst = (const int*)d_in[10];

    const int n = in_sizes[0] / DD;   // 100000
    const int E = in_sizes[9];        // 1600000

    float* out = (float*)d_out;
    float* ns_out = out;                          // [n, H, DH]
    float* attn_out = out + (size_t)n * DD;       // [E, H]

    // One-time host resource init (no device memory involved).
    static cudaStream_t sB = nullptr;
    static cudaEvent_t eFork = nullptr, eJoin = nullptr;
    if (sB == nullptr) {
        cudaStreamCreateWithFlags(&sB, cudaStreamNonBlocking);
        cudaEventCreateWithFlags(&eFork, cudaEventDisableTiming);
        cudaEventCreateWithFlags(&eJoin, cudaEventDisableTiming);
        cudaFuncSetAttribute(qkv_gemm_tc,
                             cudaFuncAttributeMaxDynamicSharedMemorySize,
                             GEMM_SMEM);
    }

    const int nb = (n + 1023) / 1024;

    // Fork: CSR chain on side stream, GEMM on main stream (concurrent).
    cudaEventRecord(eFork, 0);
    cudaStreamWaitEvent(sB, eFork, 0);

    hist_kernel<<<(E + 255) / 256, 256, 0, sB>>>(dst, E);
    scan1<<<nb, 1024, 0, sB>>>(n);
    scan3<<<nb, 1024, 0, sB>>>(n, E);

    qkv_gemm_tc<<<(n + 63) / 64, 256, GEMM_SMEM>>>(x, Wq, bq, Wk, bk, Wv, bv, n);  // 4th: profiled

    scatter_kernel<<<(E + 255) / 256, 256, 0, sB>>>(src, dst, E);
    cudaEventRecord(eJoin, sB);

    // Join: node_attn needs both the GEMM outputs and the CSR edge list.
    cudaStreamWaitEvent(0, eJoin, 0);
    node_attn<<<(n * 32 + 63) / 64, 64>>>(pi, vw, ns_out, attn_out, n);
}

// round 16
// speedup vs baseline: 1.1155x; 1.1155x over previous
#include <cuda_runtime.h>
#include <cuda_fp16.h>
#include <math_constants.h>

// Problem constants (fixed by the dataset)
constexpr int NN = 100000;   // nodes
constexpr int EE = 1600000;  // edges
constexpr int DD = 128;      // model dim
constexpr int HH = 8;        // heads
// DH = 16, M = 3

// ---------------- scratch (static device globals; no allocation) -------------
__device__ float  g_Q[NN * DD];
__device__ __half g_KVh[NN * 256];    // per node: K[128 halfs] then V[128 halfs]
__device__ int    g_deg[NN];
__device__ int    g_rowptr[NN + 1];
__device__ int    g_cursor[NN];
__device__ int2   g_edge[EE];         // (eid, src) packed
__device__ float  g_scores[(size_t)EE * HH];  // raw scores in CSR order
__device__ int    g_bsum[128];

// ---------------- TF32 helpers ------------------------------------------------
__device__ __forceinline__ float to_tf32(float a) {
    float r; asm("cvt.rna.tf32.f32 %0, %1;" : "=f"(r) : "f"(a)); return r;
}

__device__ __forceinline__ void mma_tf32(float c[4], const unsigned a[4],
                                         const unsigned b[2]) {
    asm volatile(
        "mma.sync.aligned.m16n8k8.row.col.f32.tf32.tf32.f32 "
        "{%0,%1,%2,%3}, {%4,%5,%6,%7}, {%8,%9}, {%0,%1,%2,%3};"
        : "+f"(c[0]), "+f"(c[1]), "+f"(c[2]), "+f"(c[3])
        : "r"(a[0]), "r"(a[1]), "r"(a[2]), "r"(a[3]), "r"(b[0]), "r"(b[1]));
}

// ---------------- QKV GEMM (TF32 tensor core, cp.async W pipeline) ------------
// R14 tile config (128x128, A resident, W double-buffered 32-k slabs). The W
// slab is fed to the MMA as RAW fp32 bits (HW truncates to tf32) — the
// per-slab conversion pass and its extra __syncthreads are removed. A is
// RNA-converted once at tile fill.
constexpr int XS = 132;            // xs row stride
constexpr int WSS = 136;           // W slab row stride
constexpr int SLABF = 32 * WSS;    // floats per slab buffer
constexpr int GEMM_SMEM = (128 * XS + 2 * SLABF) * 4;   // 102400 B

__device__ __forceinline__ void cpasync_w_slab(const float* Wsrc, float* buf,
                                               int tid) {
    unsigned sb = (unsigned)__cvta_generic_to_shared(buf);
#pragma unroll
    for (int i = 0; i < 4; ++i) {
        int idx = tid + i * 256;
        int kr = idx >> 5, c = (idx & 31) << 2;
        unsigned sa = sb + (unsigned)((kr * WSS + c) * 4);
        asm volatile("cp.async.cg.shared.global [%0], [%1], 16;\n"
                     :: "r"(sa), "l"(Wsrc + (size_t)kr * DD + c));
    }
}

__global__ __launch_bounds__(256, 2) void qkv_gemm_tc(
    const float* __restrict__ x,
    const float* __restrict__ Wq, const float* __restrict__ bq,
    const float* __restrict__ Wk, const float* __restrict__ bk,
    const float* __restrict__ Wv, const float* __restrict__ bv,
    int n)
{
    extern __shared__ float smem[];
    float* xs  = smem;               // [128 rows][XS]  tf32 (RNA) values
    float* wsb = smem + 128 * XS;    // [2][32 k][WSS]  raw fp32 W slabs

    const int tid  = threadIdx.x;
    const int lane = tid & 31;
    const int wid  = tid >> 5;
    const int warpM = wid & 3;
    const int warpN = wid >> 1 >> 1;  // wid >> 2
    const int row0 = blockIdx.x * 128;

    for (int i = tid; i < 128 * 32; i += 256) {
        int r = i >> 5, c = (i & 31) << 2;
        float4 v = make_float4(0.f, 0.f, 0.f, 0.f);
        if (row0 + r < n) v = *(const float4*)(x + (size_t)(row0 + r) * DD + c);
        xs[r * XS + c]     = to_tf32(v.x);
        xs[r * XS + c + 1] = to_tf32(v.y);
        xs[r * XS + c + 2] = to_tf32(v.z);
        xs[r * XS + c + 3] = to_tf32(v.w);
    }

    const float* Ws[3] = {Wq, Wk, Wv};
    const float* Bs[3] = {bq, bk, bv};

    const int gidx = lane >> 2;
    const int tidx = lane & 3;

    cpasync_w_slab(Ws[0], wsb, tid);
    asm volatile("cp.async.commit_group;\n");

    float C[2][8][4];

#pragma unroll 1
    for (int ls = 0; ls < 12; ++ls) {
        const int w = ls >> 2;
        const int s = ls & 3;

        if (s == 0) {
#pragma unroll
            for (int mt = 0; mt < 2; ++mt)
#pragma unroll
                for (int nt = 0; nt < 8; ++nt)
#pragma unroll
                    for (int q = 0; q < 4; ++q) C[mt][nt][q] = 0.f;
        }

        asm volatile("cp.async.wait_group 0;\n");
        __syncthreads();   // slab ls arrived; prior readers of other buf done

        if (ls < 11) {
            const int nls = ls + 1;
            cpasync_w_slab(Ws[nls >> 2] + (size_t)((nls & 3) * 32) * DD,
                           wsb + (nls & 1) * SLABF, tid);
            asm volatile("cp.async.commit_group;\n");
        }

        const float* wb = wsb + (ls & 1) * SLABF;
        // NO conversion pass: W bits fed raw to tf32 MMA (HW truncates).

#pragma unroll
        for (int k8 = 0; k8 < 4; ++k8) {
            unsigned a[2][4];
#pragma unroll
            for (int mt = 0; mt < 2; ++mt) {
                int row = warpM * 32 + mt * 16 + gidx;
                int col = s * 32 + k8 * 8 + tidx;
                a[mt][0] = __float_as_uint(xs[row * XS + col]);
                a[mt][1] = __float_as_uint(xs[(row + 8) * XS + col]);
                a[mt][2] = __float_as_uint(xs[row * XS + col + 4]);
                a[mt][3] = __float_as_uint(xs[(row + 8) * XS + col + 4]);
            }
#pragma unroll
            for (int nt = 0; nt < 8; ++nt) {
                int colb = warpN * 64 + nt * 8 + gidx;
                int krow = k8 * 8 + tidx;
                unsigned b[2];
                b[0] = __float_as_uint(wb[krow * WSS + colb]);
                b[1] = __float_as_uint(wb[(krow + 4) * WSS + colb]);
                mma_tf32(C[0][nt], a[0], b);
                mma_tf32(C[1][nt], a[1], b);
            }
        }

        if (s == 3) {
            const float* B = Bs[w];
#pragma unroll
            for (int nt = 0; nt < 8; ++nt) {
                int col = warpN * 64 + nt * 8 + 2 * tidx;
                float b0 = __ldg(B + col);
                float b1 = __ldg(B + col + 1);
#pragma unroll
                for (int mt = 0; mt < 2; ++mt) {
                    int r0 = row0 + warpM * 32 + mt * 16 + gidx;
                    int r1 = r0 + 8;
                    float o00 = C[mt][nt][0] + b0, o01 = C[mt][nt][1] + b1;
                    float o10 = C[mt][nt][2] + b0, o11 = C[mt][nt][3] + b1;
                    if (w == 0) {
                        if (r0 < n) *(float2*)(g_Q + (size_t)r0 * DD + col) =
                            make_float2(o00, o01);
                        if (r1 < n) *(float2*)(g_Q + (size_t)r1 * DD + col) =
                            make_float2(o10, o11);
                    } else {
                        int off = (w == 1) ? 0 : 128;
                        if (r0 < n)
                            *(__half2*)(g_KVh + (size_t)r0 * 256 + off + col) =
                                __floats2half2_rn(o00, o01);
                        if (r1 < n)
                            *(__half2*)(g_KVh + (size_t)r1 * 256 + off + col) =
                                __floats2half2_rn(o10, o11);
                    }
                }
            }
        }
        __syncthreads();   // done reading wb before it's refilled
    }
}

// ---------------- CSR construction -------------------------------------------
__global__ void hist_kernel(const int* __restrict__ dst, int E) {
    int i = blockIdx.x * blockDim.x + threadIdx.x;
    if (i < E) atomicAdd(&g_deg[dst[i]], 1);
}

__global__ __launch_bounds__(1024) void scan1(int n) {
    __shared__ int sm[1024];
    const int t = threadIdx.x;
    const int i = blockIdx.x * 1024 + t;
    int v = (i < n) ? g_deg[i] : 0;
    if (i < n) g_deg[i] = 0;
    sm[t] = v;
    __syncthreads();
    for (int off = 1; off < 1024; off <<= 1) {
        int u = (t >= off) ? sm[t - off] : 0;
        __syncthreads();
        sm[t] += u;
        __syncthreads();
    }
    if (i < n) g_rowptr[i] = sm[t] - v;
    if (t == 1023) g_bsum[blockIdx.x] = sm[t];
}

__global__ __launch_bounds__(1024) void scan3(int n, int E) {
    __shared__ int soff;
    const int t = threadIdx.x;
    if (t == 0) soff = 0;
    __syncthreads();
    int acc = 0;
    for (int j = t; j < blockIdx.x; j += 1024) acc += g_bsum[j];
    if (acc) atomicAdd(&soff, acc);
    __syncthreads();
    const int i = blockIdx.x * 1024 + t;
    if (i < n) {
        int r = g_rowptr[i] + soff;
        g_rowptr[i] = r;
        g_cursor[i] = r;
    }
    if (i == 0) g_rowptr[n] = E;
}

__global__ void scatter_kernel(const int* __restrict__ src,
                               const int* __restrict__ dst, int E) {
    int i = blockIdx.x * blockDim.x + threadIdx.x;
    if (i < E) {
        int p = atomicAdd(&g_cursor[dst[i]], 1);
        g_edge[p] = make_int2(i, src[i]);
    }
}

// ---------------- per-node online-softmax attention + normalization ----------
// R14 body, byte-identical: one warp per node, 64-thread blocks, online
// max-rescale softmax (the serial chain keeps register pressure low — proven
// faster than every "optimized" variant in R8/R9/R13/R15).
__global__ __launch_bounds__(64) void node_attn(
    const float* __restrict__ pi, const float* __restrict__ view_w,
    float* __restrict__ ns_out, float* __restrict__ attn_out, int n)
{
    int warp = (blockIdx.x * blockDim.x + threadIdx.x) >> 5;
    if (warp >= n) return;
    const int lane = threadIdx.x & 31;
    const int h = lane >> 2;
    const int nd = warp;
    const int dsub = lane & 3;

    const float4* Q4 = (const float4*)g_Q;
    const uint2* KVu = (const uint2*)g_KVh;   // 64 uint2 per node (512B)

    const float4 qv = Q4[nd * 32 + lane];
    const float p0 = pi[nd * 24 + h * 3 + 0];
    const float p1 = pi[nd * 24 + h * 3 + 1];
    const float p2 = pi[nd * 24 + h * 3 + 2];

    const int beg = g_rowptr[nd];
    const int end = g_rowptr[nd + 1];

    float m_run = -CUDART_INF_F;
    float s_run = 0.f;
    float ax = 0.f, ay = 0.f, az = 0.f, aw = 0.f;

    for (int j = beg; j < end; ++j) {
        const int2 e = g_edge[j];
        const int eid = e.x;
        const int sN = e.y;

        uint2 ku = KVu[(size_t)sN * 64 + lane];
        uint2 vu = KVu[(size_t)sN * 64 + 32 + lane];
        float2 k01 = __half22float2(*(__half2*)&ku.x);
        float2 k23 = __half22float2(*(__half2*)&ku.y);

        float d = qv.x * k01.x + qv.y * k01.y + qv.z * k23.x + qv.w * k23.y;
        d += __shfl_xor_sync(0xffffffff, d, 1);
        d += __shfl_xor_sync(0xffffffff, d, 2);

        float vw0 = view_w[eid * 3 + 0];
        float vw1 = view_w[eid * 3 + 1];
        float vw2 = view_w[eid * 3 + 2];
        float mix = p0 * vw0 + p1 * vw1 + p2 * vw2;

        float sc = d * 0.25f + __logf(fmaxf(mix, 1e-8f));
        if (!(mix > 0.f)) sc = -1e9f;
        if (dsub == 0) g_scores[(size_t)j * HH + h] = sc;   // sequential write

        float nm = fmaxf(m_run, sc);
        float scale = __expf(m_run - nm);
        float p = (sc > -1e8f) ? __expf(sc - nm) : 0.f;
        float2 v01 = __half22float2(*(__half2*)&vu.x);
        float2 v23 = __half22float2(*(__half2*)&vu.y);
        s_run = s_run * scale + p;
        ax = ax * scale + p * v01.x;
        ay = ay * scale + p * v01.y;
        az = az * scale + p * v23.x;
        aw = aw * scale + p * v23.y;
        m_run = nm;
    }

    float inv = 1.f / fmaxf(s_run, 1e-8f);
    ((float4*)ns_out)[nd * 32 + lane] = make_float4(ax * inv, ay * inv,
                                                    az * inv, aw * inv);

    // sweep 2: normalize scores -> attn_out. 4 edges per iteration.
    const int h2 = lane & 7;
    const float m_h = __shfl_sync(0xffffffff, m_run, h2 << 2);
    const float i_h = __shfl_sync(0xffffffff, inv,   h2 << 2);
    for (int j0 = beg; j0 < end; j0 += 4) {
        int j = j0 + (lane >> 3);
        if (j < end) {
            int eid = g_edge[j].x;
            float sc = g_scores[(size_t)j * HH + h2];
            float a = (sc > -1e8f) ? __expf(sc - m_h) * i_h : 0.f;
            attn_out[(size_t)eid * HH + h2] = a;
        }
    }
}

// ---------------- launch ------------------------------------------------------
extern "C" void kernel_launch(void* const* d_in, const int* in_sizes, int n_in,
                              void* d_out, int out_size) {
    const float* x   = (const float*)d_in[0];
    const float* pi  = (const float*)d_in[1];
    const float* vw  = (const float*)d_in[2];
    const float* Wq  = (const float*)d_in[3];
    const float* bq  = (const float*)d_in[4];
    const float* Wk  = (const float*)d_in[5];
    const float* bk  = (const float*)d_in[6];
    const float* Wv  = (const float*)d_in[7];
    const float* bv  = (const float*)d_in[8];
    const int*   src = (const int*)d_in[9];
    const int*   dst = (const int*)d_in[10];

    const int n = in_sizes[0] / DD;   // 100000
    const int E = in_sizes[9];        // 1600000

    float* out = (float*)d_out;
    float* ns_out = out;                          // [n, H, DH]
    float* attn_out = out + (size_t)n * DD;       // [E, H]

    // One-time host resource init (no device memory involved).
    static cudaStream_t sB = nullptr;
    static cudaEvent_t eFork = nullptr, eJoin = nullptr;
    if (sB == nullptr) {
        cudaStreamCreateWithFlags(&sB, cudaStreamNonBlocking);
        cudaEventCreateWithFlags(&eFork, cudaEventDisableTiming);
        cudaEventCreateWithFlags(&eJoin, cudaEventDisableTiming);
        cudaFuncSetAttribute(qkv_gemm_tc,
                             cudaFuncAttributeMaxDynamicSharedMemorySize,
                             GEMM_SMEM);
    }

    const int nb = (n + 1023) / 1024;

    // Fork: CSR chain on side stream, GEMM on main stream (concurrent).
    cudaEventRecord(eFork, 0);
    cudaStreamWaitEvent(sB, eFork, 0);

    hist_kernel<<<(E + 255) / 256, 256, 0, sB>>>(dst, E);
    scan1<<<nb, 1024, 0, sB>>>(n);
    scan3<<<nb, 1024, 0, sB>>>(n, E);

    qkv_gemm_tc<<<(n + 127) / 128, 256, GEMM_SMEM>>>(x, Wq, bq, Wk, bk, Wv, bv, n);  // 4th: profiled

    scatter_kernel<<<(E + 255) / 256, 256, 0, sB>>>(src, dst, E);
    cudaEventRecord(eJoin, sB);

    // Join: node_attn needs both the GEMM outputs and the CSR edge list.
    cudaStreamWaitEvent(0, eJoin, 0);
    node_attn<<<(n * 32 + 63) / 64, 64>>>(pi, vw, ns_out, attn_out, n);
}